// round 7
// baseline (speedup 1.0000x reference)
#include <cuda_runtime.h>
#include <cuda_bf16.h>
#include <cstdint>

// Nearest-of-16-sorted-qpoints quantizer, round 5.
// R2/R4 plateau at DRAM ~78%: LSU-issue-bound (32 LDS + 8 LDG + 24 STG cyc
// per warp-task vs 48-cyc DRAM budget). R5: first 3 search levels in
// registers (7 midpoints, FSETP/FSEL), then two INDEPENDENT shared fetches:
//   LDS.32 mid[i]  and  LDS.64 (qp[i], qp[i+1])   (i even -> aligned,
// disjoint bank pairs -> conflict-free). 2 shared ops/element instead of 4.
// Semantics identical to R2 (idx = #{j : x > mid[j]}, ties -> left point).

struct Luts {
    float m1, m3, m5, m7, m9, m11, m13;  // register-resident midpoints
};

__device__ __forceinline__ float quant1(float v, const Luts& L,
                                        const float* __restrict__ s_mid,
                                        const float2* __restrict__ s_qp2)
{
    // Levels 0-2: register-only binary search over midpoints.
    bool p0 = v > L.m7;
    float mB = p0 ? L.m11 : L.m3;
    bool p1 = v > mB;
    float mC1 = p0 ? L.m9  : L.m1;
    float mC2 = p0 ? L.m13 : L.m5;
    float mC  = p1 ? mC2 : mC1;
    bool p2 = v > mC;

    // Partial index i in {0,2,...,14}
    int i = (p0 ? 8 : 0) + (p1 ? 4 : 0) + (p2 ? 2 : 0);

    // Two independent shared fetches (no LDS->LDS chain):
    float  mD   = s_mid[i];          // level-3 midpoint
    float2 pair = s_qp2[i >> 1];     // (qp[i], qp[i+1]), 8B-aligned LDS.64

    return (v > mD) ? pair.y : pair.x;
}

__global__ __launch_bounds__(256, 7) void QPointQuantize_kernel(
    const float4* __restrict__ x,
    const float* __restrict__ q,
    float4* __restrict__ out,
    int n4)
{
    __shared__ float s_qp[16];       // qp pairs read via float2*
    __shared__ float s_mid[16];      // 15 used (even indices hit in hot path)

    if (threadIdx.x < 16)
        s_qp[threadIdx.x] = q[threadIdx.x];
    __syncthreads();
    if (threadIdx.x < 15)
        s_mid[threadIdx.x] = 0.5f * (s_qp[threadIdx.x] + s_qp[threadIdx.x + 1]);
    __syncthreads();

    Luts L;
    L.m1  = s_mid[1];  L.m3  = s_mid[3];  L.m5  = s_mid[5];
    L.m7  = s_mid[7];  L.m9  = s_mid[9];  L.m11 = s_mid[11];
    L.m13 = s_mid[13];

    const float2* s_qp2 = reinterpret_cast<const float2*>(s_qp);

    // 2 float4 per thread, coalesced, front-batched loads (MLP_p1=2).
    int base = blockIdx.x * (256 * 2) + threadIdx.x;

    if (base + 256 < n4) {
        float4 v0 = __ldcs(&x[base]);
        float4 v1 = __ldcs(&x[base + 256]);

        float4 o0, o1;
        o0.x = quant1(v0.x, L, s_mid, s_qp2);
        o0.y = quant1(v0.y, L, s_mid, s_qp2);
        o0.z = quant1(v0.z, L, s_mid, s_qp2);
        o0.w = quant1(v0.w, L, s_mid, s_qp2);
        o1.x = quant1(v1.x, L, s_mid, s_qp2);
        o1.y = quant1(v1.y, L, s_mid, s_qp2);
        o1.z = quant1(v1.z, L, s_mid, s_qp2);
        o1.w = quant1(v1.w, L, s_mid, s_qp2);

        __stcs(&out[base],       o0);
        __stcs(&out[base + 256], o1);
    } else {
        for (int k = 0; k < 2; k++) {
            int idx = base + k * 256;
            if (idx < n4) {
                float4 v = __ldcs(&x[idx]);
                float4 o;
                o.x = quant1(v.x, L, s_mid, s_qp2);
                o.y = quant1(v.y, L, s_mid, s_qp2);
                o.z = quant1(v.z, L, s_mid, s_qp2);
                o.w = quant1(v.w, L, s_mid, s_qp2);
                __stcs(&out[idx], o);
            }
        }
    }
}

extern "C" void kernel_launch(void* const* d_in, const int* in_sizes, int n_in,
                              void* d_out, int out_size)
{
    const float* x = (const float*)d_in[0];   // (64, 1024, 1024) fp32
    const float* q = (const float*)d_in[1];   // (16,) fp32 sorted
    float* out = (float*)d_out;

    int n = in_sizes[0];          // 67,108,864
    int n4 = n >> 2;              // 16,777,216 float4s

    int threads = 256;
    int elems_per_block = threads * 2;                     // 512 float4s
    int blocks = (n4 + elems_per_block - 1) / elems_per_block;  // 32,768

    QPointQuantize_kernel<<<blocks, threads>>>(
        (const float4*)x, q, (float4*)out, n4);
}

// round 8
// speedup vs baseline: 1.0196x; 1.0196x over previous
#include <cuda_runtime.h>
#include <cuda_bf16.h>
#include <cstdint>

// Nearest-of-16-sorted-qpoints quantizer, round 6.
// Model: warp-task (8 elems) LSU cost was 32 LDS + 8 LDG.128 + 24 STG.128
// = 64 cyc vs 48-cyc DRAM budget -> LSU-bound at DRAM ~78% (R2/R4/R5 all).
// R6: Blackwell 256-bit global ld/st (ld/st.global.cs.v8.f32) -> one
// LDG.E.256 + one STG.E.256 per thread. LSU drops to ~48 cyc; DRAM binds.
// Quantizer is exactly R4's proven 4-level LDS binary search (rel_err==0).

__device__ __forceinline__ float quant1(float v, float m7,
                                        const float* __restrict__ s_mid,
                                        const float* __restrict__ s_qp)
{
    int i = (v > m7) ? 8 : 0;              // level 0: uniform register compare
    i += (v > s_mid[i + 3]) ? 4 : 0;       // level 1: LDS
    i += (v > s_mid[i + 1]) ? 2 : 0;       // level 2: LDS
    i += (v > s_mid[i]) ? 1 : 0;           // level 3: LDS
    return s_qp[i];                         // value LUT: LDS broadcast
}

__global__ __launch_bounds__(256, 7) void QPointQuantize_kernel(
    const float* __restrict__ x,
    const float* __restrict__ q,
    float* __restrict__ out,
    int n)   // n = total elements (multiple of 8 per launch config)
{
    __shared__ float s_qp[16];
    __shared__ float s_mid[16];   // 15 used; banks 0-14, conflict-free

    if (threadIdx.x < 16)
        s_qp[threadIdx.x] = q[threadIdx.x];
    __syncthreads();
    if (threadIdx.x < 15)
        s_mid[threadIdx.x] = 0.5f * (s_qp[threadIdx.x] + s_qp[threadIdx.x + 1]);
    __syncthreads();

    const float m7 = s_mid[7];    // uniform -> register, skips one LDS level

    // 8 contiguous floats (32 bytes) per thread via one 256-bit access.
    long long base = (long long)(blockIdx.x * 256 + threadIdx.x) * 8;
    if (base + 8 > n) return;     // exact divide for this shape; safety only

    const float* xp = x + base;
    float*       op = out + base;

    float v0, v1, v2, v3, v4, v5, v6, v7;
    asm volatile(
        "ld.global.cs.v8.f32 {%0,%1,%2,%3,%4,%5,%6,%7}, [%8];"
        : "=f"(v0), "=f"(v1), "=f"(v2), "=f"(v3),
          "=f"(v4), "=f"(v5), "=f"(v6), "=f"(v7)
        : "l"(xp));

    float o0 = quant1(v0, m7, s_mid, s_qp);
    float o1 = quant1(v1, m7, s_mid, s_qp);
    float o2 = quant1(v2, m7, s_mid, s_qp);
    float o3 = quant1(v3, m7, s_mid, s_qp);
    float o4 = quant1(v4, m7, s_mid, s_qp);
    float o5 = quant1(v5, m7, s_mid, s_qp);
    float o6 = quant1(v6, m7, s_mid, s_qp);
    float o7 = quant1(v7, m7, s_mid, s_qp);

    asm volatile(
        "st.global.cs.v8.f32 [%0], {%1,%2,%3,%4,%5,%6,%7,%8};"
        :: "l"(op),
           "f"(o0), "f"(o1), "f"(o2), "f"(o3),
           "f"(o4), "f"(o5), "f"(o6), "f"(o7)
        : "memory");
}

extern "C" void kernel_launch(void* const* d_in, const int* in_sizes, int n_in,
                              void* d_out, int out_size)
{
    const float* x = (const float*)d_in[0];   // (64, 1024, 1024) fp32
    const float* q = (const float*)d_in[1];   // (16,) fp32 sorted
    float* out = (float*)d_out;

    int n = in_sizes[0];          // 67,108,864 (divisible by 8)

    int threads = 256;
    int elems_per_block = threads * 8;                    // 2048 elements
    int blocks = (n + elems_per_block - 1) / elems_per_block;  // 32,768

    QPointQuantize_kernel<<<blocks, threads>>>(x, q, out, n);
}